// round 13
// baseline (speedup 1.0000x reference)
#include <cuda_runtime.h>
#include <cuda_bf16.h>

#define B_   32
#define N_   300
#define H_   1024
#define W_   1024
#define HW_  (1024 * 1024)
#define NCHUNK   128                 // row-chunks per batch (8 rows each)
#define TOTCHUNK (B_ * NCHUNK)       // 4096
#define SLOTS    256                 // edge chunks collect ~110 clamped corners; 256 safe
#define NGRP     32                  // 32-column groups per row
#define TOTGRP   (B_ * NGRP)         // 1024
#define SLOTS2   256                 // edge col-group collects ~140; 256 safe
#define NQ       (B_ * N_ * 4)       // 38400 corner slots
#define NB       (B_ * N_)           // 9600 boxes

// Fixed-point scale for the deterministic integer reduction.
// per_box <= 1, so sum < 9600 * 2^44 ~= 2^57.3 << 2^64. Quant err ~ 2^-44/item.
#define ACC_SCALE 17592186044416.0   // 2^44

// Scratch (static device arrays — no allocation). Zero-initialized at load.
__device__ float g_agg[(size_t)TOTCHUNK * W_];   // 16 MB: chunk column aggregates
__device__ float g_corner[NQ];                   // corner values (local, then +prefix)
__device__ int   g_cnt[TOTCHUNK];                // row-chunk bucket counters
__device__ int   g_bucket[TOTCHUNK * SLOTS];
__device__ int   g_cnt2[TOTGRP];                 // column-group bucket counters
__device__ int   g_bucket2[TOTGRP * SLOTS2];
__device__ unsigned long long g_acc;             // fixed-point global accumulator
__device__ unsigned int g_done;                  // last-block ticket

__device__ __forceinline__ int to_idx(float v, int m) {
    int i = (int)v;                  // trunc toward zero == jnp.trunc -> int32
    if (i < 0) i = 0;
    if (i > m - 1) i = m - 1;
    return i;
}

// ---------------------------------------------------------------------------
// K1: bucket corner queries two ways:
//   row bucket   (batch, row-chunk):    qid[0:17) | x[17:27)    | r[27:30)
//   col bucket   (batch, column-group): qid[0:17) | xl[17:22)   | c[22:29)
// Relies on counters == 0 (zeroed at load, re-zeroed by boxKernel's last block).
// ---------------------------------------------------------------------------
__global__ void bucketKernel(const float* __restrict__ boxes,
                             const float* __restrict__ conf) {
    int i = blockIdx.x * blockDim.x + threadIdx.x;
    if (i >= NB) return;
    int b = i / N_;
    float4 bx = ((const float4*)boxes)[i];
    float cx = bx.x, cy = bx.y, w = bx.z, h = bx.w;
    float cf = conf[i];

    int x1 = to_idx((cx - 0.5f * w) * (float)W_, W_);
    int x2 = to_idx((cx + 0.5f * w) * (float)W_, W_);
    int y1 = to_idx((cy - 0.5f * h) * (float)H_, H_);
    int y2 = to_idx((cy + 0.5f * h) * (float)H_, H_);
    if (!(cf >= 0.3f && x2 > x1 && y2 > y1)) return;

    int ys[4] = {y2, y1, y2, y1};
    int xs[4] = {x2, x2, x1, x1};
    #pragma unroll
    for (int k = 0; k < 4; k++) {
        int yy = ys[k], xx = xs[k];
        if (yy > 0 && xx > 0) {
            int r = (yy - 1) & 7;
            int c = (yy - 1) >> 3;
            int x = xx - 1;
            int qid = 4 * i + k;

            int chunk = b * NCHUNK + c;
            int slot = atomicAdd(&g_cnt[chunk], 1);
            if (slot < SLOTS)
                g_bucket[chunk * SLOTS + slot] = qid | (x << 17) | (r << 27);

            int grp = b * NGRP + (x >> 5);
            int slot2 = atomicAdd(&g_cnt2[grp], 1);
            if (slot2 < SLOTS2)
                g_bucket2[grp * SLOTS2 + slot2] = qid | ((x & 31) << 17) | (c << 22);
        }
    }
}

// ---------------------------------------------------------------------------
// K2: per-chunk local prefix. One block = one (b, 8-row chunk).
// Writes chunk column aggregates to g_agg and the chunk-LOCAL corner value
// to g_corner (=).
// ---------------------------------------------------------------------------
__global__ void __launch_bounds__(256) scanChunk(const float* __restrict__ seg) {
    __shared__ float sm[8 * W_];     // 32 KB: row-wise prefix sums
    int chunk = blockIdx.x;
    int b = chunk >> 7;
    int c = chunk & (NCHUNK - 1);
    int t = threadIdx.x;
    int lane = t & 31, wrow = t >> 5;
    int y = c * 8 + wrow;

    const float* p1 = seg + ((size_t)b * 3 + 1) * HW_ + (size_t)y * W_;
    const float* p2 = seg + ((size_t)b * 3 + 2) * HW_ + (size_t)y * W_;

    float carry = 0.0f;
    #pragma unroll
    for (int half = 0; half < 2; half++) {
        float4 d[4];
        #pragma unroll
        for (int i = 0; i < 4; i++) {
            int col = (half * 4 + i) * 128 + lane * 4;
            float4 a  = __ldcs((const float4*)(p1 + col));
            float4 bb = __ldcs((const float4*)(p2 + col));
            d[i] = make_float4(bb.x - a.x, bb.y - a.y, bb.z - a.z, bb.w - a.w);
        }
        #pragma unroll
        for (int i = 0; i < 4; i++) {
            float4 v = d[i];
            float s1 = v.x + v.y, s2 = s1 + v.z, s3 = s2 + v.w;
            float tot = s3;
            #pragma unroll
            for (int o = 1; o < 32; o <<= 1) {
                float n = __shfl_up_sync(0xFFFFFFFFu, tot, o);
                if (lane >= o) tot += n;
            }
            float excl = carry + (tot - s3);
            *(float4*)(&sm[wrow * W_ + (half * 4 + i) * 128 + lane * 4]) =
                make_float4(excl + v.x, excl + s1, excl + s2, excl + s3);
            carry += __shfl_sync(0xFFFFFFFFu, tot, 31);
        }
    }
    __syncthreads();

    // column aggregate over the 8 rows; registers only
    int x0 = t * 4;
    float4 acc = make_float4(0.f, 0.f, 0.f, 0.f);
    #pragma unroll
    for (int r = 0; r < 8; r++) {
        float4 v = *(float4*)(&sm[r * W_ + x0]);
        acc.x += v.x; acc.y += v.y; acc.z += v.z; acc.w += v.w;
    }
    *(float4*)(&g_agg[(size_t)chunk * W_ + x0]) = acc;

    // answer this chunk's queries: local ii(r,x) = sum_{r'<=r} rowprefix[r'][x]
    int cnt = g_cnt[chunk];
    if (cnt > SLOTS) cnt = SLOTS;
    for (int q = t; q < cnt; q += 256) {
        int e   = g_bucket[chunk * SLOTS + q];
        int qid = e & 0x1FFFF;
        int x   = (e >> 17) & 0x3FF;
        int r   = (e >> 27) & 7;
        float s = 0.0f;
        for (int rr = 0; rr <= r; rr++)
            s += sm[rr * W_ + x];
        g_corner[qid] = s;
    }
}

// ---------------------------------------------------------------------------
// K2b: chunk-exclusive-prefix + query answer, fused. One block = one
// (b, 32-column group). Per-column prefixes over 128 chunks are built in
// smem (16 KB) and this group's corner queries get += prefix. g_agg is
// READ-ONLY here (no 16 MB write-back, no scattered gathers later).
// Fixed per-column addition order => deterministic.
// ---------------------------------------------------------------------------
__global__ void __launch_bounds__(256) chunkScan() {
    __shared__ float sums[8][32];
    __shared__ float pre[NCHUNK][32];    // exclusive prefix per (chunk, column)
    int blk  = blockIdx.x;               // 0..1023
    int b    = blk >> 5;
    int xg   = blk & 31;
    int lane = threadIdx.x & 31;
    int seg  = threadIdx.x >> 5;         // 16-chunk segment 0..7
    int x    = xg * 32 + lane;

    const float* base = g_agg + (size_t)b * NCHUNK * W_ + x;

    float v[16];
    #pragma unroll
    for (int j = 0; j < 16; j++)
        v[j] = base[(size_t)(seg * 16 + j) * W_];

    float tot = 0.0f;
    #pragma unroll
    for (int j = 0; j < 16; j++) tot += v[j];

    sums[seg][lane] = tot;
    __syncthreads();

    float E = 0.0f;
    #pragma unroll
    for (int s = 0; s < 8; s++)
        if (s < seg) E += sums[s][lane];

    #pragma unroll
    for (int j = 0; j < 16; j++) {
        pre[seg * 16 + j][lane] = E;     // exclusive prefix at chunk seg*16+j
        E += v[j];
    }
    __syncthreads();

    // add chunk-prefix to this group's corner queries
    int grp = b * NGRP + xg;
    int cnt = g_cnt2[grp];
    if (cnt > SLOTS2) cnt = SLOTS2;
    for (int q = threadIdx.x; q < cnt; q += 256) {
        int e   = g_bucket2[grp * SLOTS2 + q];
        int qid = e & 0x1FFFF;
        int xl  = (e >> 17) & 31;
        int c   = (e >> 22) & 127;
        g_corner[qid] += pre[c][xl];
    }
}

// ---------------------------------------------------------------------------
// K3: per-box combine + finalize (fused). Deterministic via exact fixed-point
// integer atomics; last block writes out and resets scratch for next replay.
// ---------------------------------------------------------------------------
__global__ void __launch_bounds__(256) boxKernel(const float* __restrict__ boxes,
                                                 const float* __restrict__ conf,
                                                 float* __restrict__ out) {
    int i = blockIdx.x * blockDim.x + threadIdx.x;
    unsigned long long q = 0ull;

    if (i < NB) {
        float4 bx = ((const float4*)boxes)[i];
        float cx = bx.x, cy = bx.y, w = bx.z, h = bx.w;
        float cf = conf[i];

        int x1 = to_idx((cx - 0.5f * w) * (float)W_, W_);
        int x2 = to_idx((cx + 0.5f * w) * (float)W_, W_);
        int y1 = to_idx((cy - 0.5f * h) * (float)H_, H_);
        int y2 = to_idx((cy + 0.5f * h) * (float)H_, H_);

        if (cf >= 0.3f && x2 > x1 && y2 > y1) {
            float area = (float)((y2 - y1) * (x2 - x1));
            float4 cr = ((const float4*)g_corner)[i];   // 4 corners, contiguous
            int ys[4] = {y2, y1, y2, y1};
            int xs[4] = {x2, x2, x1, x1};
            const float sg[4] = {1.f, -1.f, -1.f, 1.f};
            const float cv[4] = {cr.x, cr.y, cr.z, cr.w};
            float s = 0.0f;
            #pragma unroll
            for (int k = 0; k < 4; k++)
                if (ys[k] > 0 && xs[k] > 0)
                    s += sg[k] * cv[k];
            double pb = (double)(fmaxf(s / area, 0.0f) * cf);
            q = (unsigned long long)(pb * ACC_SCALE + 0.5);   // exact quantize
        }
    }

    // exact integer warp reduction, one atomic per warp
    #pragma unroll
    for (int o = 16; o > 0; o >>= 1)
        q += __shfl_down_sync(0xFFFFFFFFu, q, o);
    if ((threadIdx.x & 31) == 0 && q)
        atomicAdd(&g_acc, q);

    // last-block finalize
    __shared__ unsigned int s_ticket;
    __threadfence();
    __syncthreads();
    if (threadIdx.x == 0)
        s_ticket = atomicAdd(&g_done, 1u);
    __syncthreads();
    if (s_ticket == gridDim.x - 1) {
        int t = threadIdx.x;
        for (int j = t; j < TOTCHUNK; j += 256) g_cnt[j] = 0;
        for (int j = t; j < TOTGRP;  j += 256) g_cnt2[j] = 0;
        if (t == 0) {
            unsigned long long total = atomicAdd(&g_acc, 0ull);
            out[0] = (float)((double)total / ACC_SCALE / (double)NB);
            g_acc = 0ull;
            g_done = 0u;
        }
    }
}

// ---------------------------------------------------------------------------
extern "C" void kernel_launch(void* const* d_in, const int* in_sizes, int n_in,
                              void* d_out, int out_size) {
    const float* det_boxes = (const float*)d_in[0];   // (32,300,4)
    const float* det_conf  = (const float*)d_in[1];   // (32,300)
    const float* seg_masks = (const float*)d_in[2];   // (32,3,1024,1024)
    float* out = (float*)d_out;

    bucketKernel<<<(NB + 255) / 256, 256>>>(det_boxes, det_conf);
    scanChunk<<<TOTCHUNK, 256>>>(seg_masks);
    chunkScan<<<TOTGRP, 256>>>();
    boxKernel<<<(NB + 255) / 256, 256>>>(det_boxes, det_conf, out);
}